// round 1
// baseline (speedup 1.0000x reference)
#include <cuda_runtime.h>

// ICFM: factorization-machine interaction scoring + ragged segment sum.
// Inputs (metadata order):
//  0: intr_idxs int32 [T]
//  1: intr_divs f32   [T]
//  2: feat_idxs int32 [T,2]
//  3: seg_ids   int32 [T]   (sorted)
//  4: vecs      f32   [500000,64]
//  5: intr_W    f32   [1024]
//  6: intr_b    f32   [1]
// Output: f32 [16384]

#define NSEG 16384

__global__ void icfm_zero(float* __restrict__ out) {
    int i = blockIdx.x * blockDim.x + threadIdx.x;
    if (i < NSEG) out[i] = 0.0f;
}

__global__ void __launch_bounds__(256) icfm_main(
    const int*    __restrict__ intr_idxs,
    const float*  __restrict__ intr_divs,
    const int2*   __restrict__ feat_idxs,
    const int*    __restrict__ seg_ids,
    const float2* __restrict__ vecs,     // [N_FEATS, 32] as float2
    const float*  __restrict__ intr_W,
    const float*  __restrict__ intr_b,
    float*        __restrict__ out,
    int T)
{
    const int gwarp = (blockIdx.x * blockDim.x + threadIdx.x) >> 5;
    const int lane  = threadIdx.x & 31;
    if (gwarp >= T) return;

    // Two gathered rows, 8 B per lane, fully coalesced across the warp.
    const int2 f = __ldg(&feat_idxs[gwarp]);
    const float2 a = __ldg(&vecs[(long long)f.x * 32 + lane]);
    const float2 b = __ldg(&vecs[(long long)f.y * 32 + lane]);

    float p = a.x * b.x + a.y * b.y;
    #pragma unroll
    for (int off = 16; off > 0; off >>= 1)
        p += __shfl_xor_sync(0xffffffffu, p, off);

    if (lane == 0) {
        const float w   = __ldg(&intr_W[__ldg(&intr_idxs[gwarp])]);
        const float div = __ldg(&intr_divs[gwarp]);
        const float v   = w / div * p + __ldg(&intr_b[0]);
        atomicAdd(&out[__ldg(&seg_ids[gwarp])], v);
    }
}

extern "C" void kernel_launch(void* const* d_in, const int* in_sizes, int n_in,
                              void* d_out, int out_size) {
    const int*    intr_idxs = (const int*)   d_in[0];
    const float*  intr_divs = (const float*) d_in[1];
    const int2*   feat_idxs = (const int2*)  d_in[2];
    const int*    seg_ids   = (const int*)   d_in[3];
    const float2* vecs      = (const float2*)d_in[4];
    const float*  intr_W    = (const float*) d_in[5];
    const float*  intr_b    = (const float*) d_in[6];
    float*        out       = (float*)d_out;

    const int T = in_sizes[0];

    icfm_zero<<<(NSEG + 255) / 256, 256>>>(out);

    // 1 warp per interaction, 8 warps (256 threads) per block.
    const int warps_per_block = 256 / 32;
    const int blocks = (T + warps_per_block - 1) / warps_per_block;
    icfm_main<<<blocks, 256>>>(intr_idxs, intr_divs, feat_idxs, seg_ids,
                               vecs, intr_W, intr_b, out, T);
}

// round 2
// speedup vs baseline: 2.4499x; 2.4499x over previous
#include <cuda_runtime.h>

// ICFM: factorization-machine interaction scoring + ragged segment sum.
// Inputs (metadata order):
//  0: intr_idxs int32 [T]
//  1: intr_divs f32   [T]
//  2: feat_idxs int32 [T,2]
//  3: seg_ids   int32 [T]   (sorted)
//  4: vecs      f32   [500000,64]
//  5: intr_W    f32   [1024]
//  6: intr_b    f32   [1]
// Output: f32 [16384]
//
// v2: 16 lanes per interaction (float4 = 16B/lane, row = 256B), 2 interactions
// per warp-slot, 4 slots unrolled => 8 interactions/warp, 8 row-gathers
// batched up front for MLP=8 (v1 had MLP=2 and was latency-bound: all pipe
// utilizations < 25%).

#define NSEG 16384
#define UNROLL 4   // slots per warp; interactions per warp = 2*UNROLL

__global__ void icfm_zero(float* __restrict__ out) {
    int i = blockIdx.x * blockDim.x + threadIdx.x;
    if (i < NSEG) out[i] = 0.0f;
}

__global__ void __launch_bounds__(256) icfm_main(
    const int*    __restrict__ intr_idxs,
    const float*  __restrict__ intr_divs,
    const int2*   __restrict__ feat_idxs,
    const int*    __restrict__ seg_ids,
    const float4* __restrict__ vecs,     // [N_FEATS, 16] as float4
    const float*  __restrict__ intr_W,
    const float*  __restrict__ intr_b,
    float*        __restrict__ out,
    int T)
{
    const int gwarp = (blockIdx.x * blockDim.x + threadIdx.x) >> 5;
    const int lane  = threadIdx.x & 31;
    const int group = lane >> 4;      // 0 or 1: which interaction of the pair
    const int sub   = lane & 15;      // position within the 256B row

    const int base = gwarp * (2 * UNROLL);
    if (base >= T) return;

    // Batch all index loads, then all row gathers (8 independent LDG.128).
    int2 f[UNROLL];
    #pragma unroll
    for (int it = 0; it < UNROLL; it++) {
        int j = base + it * 2 + group;
        f[it] = (j < T) ? __ldg(&feat_idxs[j]) : make_int2(0, 0);
    }

    float4 a[UNROLL], b[UNROLL];
    #pragma unroll
    for (int it = 0; it < UNROLL; it++) {
        a[it] = __ldg(&vecs[(long long)f[it].x * 16 + sub]);
        b[it] = __ldg(&vecs[(long long)f[it].y * 16 + sub]);
    }

    const float bias = __ldg(&intr_b[0]);

    #pragma unroll
    for (int it = 0; it < UNROLL; it++) {
        float p = a[it].x * b[it].x + a[it].y * b[it].y
                + a[it].z * b[it].z + a[it].w * b[it].w;
        // Reduce within the 16-lane group (4 steps).
        #pragma unroll
        for (int off = 8; off > 0; off >>= 1)
            p += __shfl_xor_sync(0xffffffffu, p, off);

        const int j = base + it * 2 + group;
        if (sub == 0 && j < T) {
            const float w   = __ldg(&intr_W[__ldg(&intr_idxs[j])]);
            const float div = __ldg(&intr_divs[j]);
            atomicAdd(&out[__ldg(&seg_ids[j])], w / div * p + bias);
        }
    }
}

extern "C" void kernel_launch(void* const* d_in, const int* in_sizes, int n_in,
                              void* d_out, int out_size) {
    const int*    intr_idxs = (const int*)   d_in[0];
    const float*  intr_divs = (const float*) d_in[1];
    const int2*   feat_idxs = (const int2*)  d_in[2];
    const int*    seg_ids   = (const int*)   d_in[3];
    const float4* vecs      = (const float4*)d_in[4];
    const float*  intr_W    = (const float*) d_in[5];
    const float*  intr_b    = (const float*) d_in[6];
    float*        out       = (float*)d_out;

    const int T = in_sizes[0];

    icfm_zero<<<(NSEG + 255) / 256, 256>>>(out);

    const int intr_per_warp  = 2 * UNROLL;
    const int warps_per_blk  = 256 / 32;
    const int intr_per_block = intr_per_warp * warps_per_blk;
    const int blocks = (T + intr_per_block - 1) / intr_per_block;
    icfm_main<<<blocks, 256>>>(intr_idxs, intr_divs, feat_idxs, seg_ids,
                               vecs, intr_W, intr_b, out, T);
}

// round 3
// speedup vs baseline: 3.1924x; 1.3031x over previous
#include <cuda_runtime.h>

// ICFM: factorization-machine interaction scoring + ragged segment sum.
// Inputs (metadata order):
//  0: intr_idxs int32 [T]
//  1: intr_divs f32   [T]
//  2: feat_idxs int32 [T,2]
//  3: seg_ids   int32 [T]   (sorted)
//  4: vecs      f32   [500000,64]
//  5: intr_W    f32   [1024]
//  6: intr_b    f32   [1]
// Output: f32 [16384]
//
// v3: persistent grid-stride warps + software-pipelined feat_idx prefetch.
// v2 was one-shot-per-warp: every warp paid the full idx->gather->reduce
// dependency chain cold for only 8 interactions. Now each warp loops ~28
// batches; the next batch's feat_idxs gather is issued before the current
// batch's compute, hiding the serial prefix of the chain.

#define NSEG 16384
#define UNROLL 4   // slots per warp-batch; interactions per batch = 2*UNROLL

__global__ void icfm_zero(float* __restrict__ out) {
    int i = blockIdx.x * blockDim.x + threadIdx.x;
    if (i < NSEG) out[i] = 0.0f;
}

__global__ void __launch_bounds__(256) icfm_main(
    const int*    __restrict__ intr_idxs,
    const float*  __restrict__ intr_divs,
    const int2*   __restrict__ feat_idxs,
    const int*    __restrict__ seg_ids,
    const float4* __restrict__ vecs,     // [N_FEATS, 16] as float4
    const float*  __restrict__ intr_W,
    const float*  __restrict__ intr_b,
    float*        __restrict__ out,
    int T)
{
    const int lane  = threadIdx.x & 31;
    const int group = lane >> 4;      // 0 or 1: which interaction of the pair
    const int sub   = lane & 15;      // position within the 256B row

    const int warp_global = (blockIdx.x * blockDim.x + threadIdx.x) >> 5;
    const int nwarps      = (gridDim.x * blockDim.x) >> 5;
    const int nbatches    = (T + 2 * UNROLL - 1) / (2 * UNROLL);

    const float bias = __ldg(&intr_b[0]);

    int batch = warp_global;
    if (batch >= nbatches) return;

    // Prologue: load feat indices for the first batch.
    int2 fc[UNROLL];
    {
        const int base = batch * (2 * UNROLL);
        #pragma unroll
        for (int it = 0; it < UNROLL; it++) {
            int j = base + it * 2 + group;
            fc[it] = (j < T) ? __ldg(&feat_idxs[j]) : make_int2(0, 0);
        }
    }

    while (batch < nbatches) {
        const int base = batch * (2 * UNROLL);
        const int nb   = batch + nwarps;

        // Issue the 8 independent row gathers for the current batch ASAP.
        float4 a[UNROLL], b[UNROLL];
        #pragma unroll
        for (int it = 0; it < UNROLL; it++) {
            a[it] = __ldg(&vecs[(long long)fc[it].x * 16 + sub]);
            b[it] = __ldg(&vecs[(long long)fc[it].y * 16 + sub]);
        }

        // Prefetch next batch's feat indices (hidden under compute below).
        int2 fn[UNROLL];
        if (nb < nbatches) {
            const int nbase = nb * (2 * UNROLL);
            #pragma unroll
            for (int it = 0; it < UNROLL; it++) {
                int j = nbase + it * 2 + group;
                fn[it] = (j < T) ? __ldg(&feat_idxs[j]) : make_int2(0, 0);
            }
        }

        // Dot products, 16-lane reductions, scale + atomic accumulate.
        #pragma unroll
        for (int it = 0; it < UNROLL; it++) {
            float p = a[it].x * b[it].x + a[it].y * b[it].y
                    + a[it].z * b[it].z + a[it].w * b[it].w;
            #pragma unroll
            for (int off = 8; off > 0; off >>= 1)
                p += __shfl_xor_sync(0xffffffffu, p, off);

            const int j = base + it * 2 + group;
            if (sub == 0 && j < T) {
                const float w   = __ldg(&intr_W[__ldg(&intr_idxs[j])]);
                const float div = __ldg(&intr_divs[j]);
                atomicAdd(&out[__ldg(&seg_ids[j])], w / div * p + bias);
            }
        }

        #pragma unroll
        for (int it = 0; it < UNROLL; it++) fc[it] = fn[it];
        batch = nb;
    }
}

extern "C" void kernel_launch(void* const* d_in, const int* in_sizes, int n_in,
                              void* d_out, int out_size) {
    const int*    intr_idxs = (const int*)   d_in[0];
    const float*  intr_divs = (const float*) d_in[1];
    const int2*   feat_idxs = (const int2*)  d_in[2];
    const int*    seg_ids   = (const int*)   d_in[3];
    const float4* vecs      = (const float4*)d_in[4];
    const float*  intr_W    = (const float*) d_in[5];
    const float*  intr_b    = (const float*) d_in[6];
    float*        out       = (float*)d_out;

    const int T = in_sizes[0];

    icfm_zero<<<(NSEG + 255) / 256, 256>>>(out);

    // Persistent-ish launch: ~4 CTAs per SM on 148 SMs.
    const int blocks = 148 * 4;
    icfm_main<<<blocks, 256>>>(intr_idxs, intr_divs, feat_idxs, seg_ids,
                               vecs, intr_W, intr_b, out, T);
}

// round 4
// speedup vs baseline: 4.7516x; 1.4884x over previous
#include <cuda_runtime.h>

// ICFM v4: lane-parallel scalars + fast divide + segment-aggregated atomics.
// v3 analysis: ~37 instr issued per interaction (FDIV expansion, serialized
// per-slot scalar chains, 1M atomics). This version cuts issue count:
//  - __fdividef (divisors are {1,2,3,4}; 1-ulp error ok vs 1e-3 tol)
//  - all 32 lanes cooperatively load scalar data for the batch's 8
//    interactions (lane&7), overlapping the vec-gather latency
//  - sorted seg_ids => most batches are segment-uniform: one atomic/batch

#define NSEG 16384
#define UNROLL 4   // slots; interactions per warp-batch = 2*UNROLL = 8

__global__ void icfm_zero(float* __restrict__ out) {
    int i = blockIdx.x * blockDim.x + threadIdx.x;
    if (i < NSEG) out[i] = 0.0f;
}

__global__ void __launch_bounds__(256, 4) icfm_main(
    const int*    __restrict__ intr_idxs,
    const float*  __restrict__ intr_divs,
    const int2*   __restrict__ feat_idxs,
    const int*    __restrict__ seg_ids,
    const float4* __restrict__ vecs,     // [N_FEATS, 16] as float4
    const float*  __restrict__ intr_W,
    const float*  __restrict__ intr_b,
    float*        __restrict__ out,
    int T)
{
    const int lane  = threadIdx.x & 31;
    const int group = lane >> 4;      // which interaction of a slot-pair
    const int sub   = lane & 15;      // position within the 256B row
    const int oct   = lane & 7;       // interaction-in-batch this lane owns (x4 replicated)

    const int warp_global = (blockIdx.x * blockDim.x + threadIdx.x) >> 5;
    const int nwarps      = (gridDim.x * blockDim.x) >> 5;
    const int nbatches    = (T + 2 * UNROLL - 1) / (2 * UNROLL);

    const float bias = __ldg(&intr_b[0]);

    int batch = warp_global;
    if (batch >= nbatches) return;

    // Prologue: feat indices for the first batch (clamped; OOB handled via v=0).
    int2 fc[UNROLL];
    {
        const int base = batch * (2 * UNROLL);
        #pragma unroll
        for (int it = 0; it < UNROLL; it++) {
            int j = base + it * 2 + group;
            fc[it] = __ldg(&feat_idxs[j < T ? j : T - 1]);
        }
    }

    while (batch < nbatches) {
        const int base = batch * (2 * UNROLL);
        const int nb   = batch + nwarps;

        // 8 independent row gathers (MLP=8), issued first.
        float4 a[UNROLL], b[UNROLL];
        #pragma unroll
        for (int it = 0; it < UNROLL; it++) {
            a[it] = __ldg(&vecs[(long long)fc[it].x * 16 + sub]);
            b[it] = __ldg(&vecs[(long long)fc[it].y * 16 + sub]);
        }

        // Lane-parallel scalar loads for this batch (overlap the gather wait).
        const int  j2     = base + oct;
        const bool valid2 = j2 < T;
        const int  j2c    = valid2 ? j2 : T - 1;
        const int  idx    = __ldg(&intr_idxs[j2c]);
        const float dv    = __ldg(&intr_divs[j2c]);
        const int  sg     = __ldg(&seg_ids[j2c]);
        const float w     = __ldg(&intr_W[idx]);
        const float coef  = __fdividef(w, dv);

        // Prefetch next batch's feat indices.
        int2 fn[UNROLL];
        if (nb < nbatches) {
            const int nbase = nb * (2 * UNROLL);
            #pragma unroll
            for (int it = 0; it < UNROLL; it++) {
                int j = nbase + it * 2 + group;
                fn[it] = __ldg(&feat_idxs[j < T ? j : T - 1]);
            }
        }

        // Dot products + 16-lane reductions; route each interaction's sum to
        // the lane that owns its scalars (lane&7 == interaction-in-batch).
        float v = 0.0f;
        #pragma unroll
        for (int it = 0; it < UNROLL; it++) {
            float p = a[it].x * b[it].x + a[it].y * b[it].y
                    + a[it].z * b[it].z + a[it].w * b[it].w;
            p += __shfl_xor_sync(0xffffffffu, p, 8);
            p += __shfl_xor_sync(0xffffffffu, p, 4);
            p += __shfl_xor_sync(0xffffffffu, p, 2);
            p += __shfl_xor_sync(0xffffffffu, p, 1);
            // p now holds this lane's-group sum in every lane of the group.
            const float q  = __shfl_xor_sync(0xffffffffu, p, 16); // other group's
            const float g0 = (lane < 16) ? p : q;  // group-0 slot sum
            const float g1 = (lane < 16) ? q : p;  // group-1 slot sum
            if ((lane & 6) == 2 * it)              // lanes owning slot 'it'
                v = (lane & 1) ? g1 : g0;
        }
        v = valid2 ? (coef * v + bias) : 0.0f;

        // Segment-aggregated accumulate: one atomic when the batch is uniform.
        const int      sg0 = __shfl_sync(0xffffffffu, sg, 0);
        const unsigned uni = __ballot_sync(0xffffffffu, sg == sg0);
        if (uni == 0xffffffffu) {
            v += __shfl_xor_sync(0xffffffffu, v, 4);
            v += __shfl_xor_sync(0xffffffffu, v, 2);
            v += __shfl_xor_sync(0xffffffffu, v, 1);
            if (lane == 0) atomicAdd(&out[sg0], v);
        } else {
            if (lane < 8) atomicAdd(&out[sg], v);
        }

        #pragma unroll
        for (int it = 0; it < UNROLL; it++) fc[it] = fn[it];
        batch = nb;
    }
}

extern "C" void kernel_launch(void* const* d_in, const int* in_sizes, int n_in,
                              void* d_out, int out_size) {
    const int*    intr_idxs = (const int*)   d_in[0];
    const float*  intr_divs = (const float*) d_in[1];
    const int2*   feat_idxs = (const int2*)  d_in[2];
    const int*    seg_ids   = (const int*)   d_in[3];
    const float4* vecs      = (const float4*)d_in[4];
    const float*  intr_W    = (const float*) d_in[5];
    const float*  intr_b    = (const float*) d_in[6];
    float*        out       = (float*)d_out;

    const int T = in_sizes[0];

    icfm_zero<<<(NSEG + 255) / 256, 256>>>(out);

    const int blocks = 148 * 4;  // persistent-ish: ~4 CTAs/SM
    icfm_main<<<blocks, 256>>>(intr_idxs, intr_divs, feat_idxs, seg_ids,
                               vecs, intr_W, intr_b, out, T);
}